// round 13
// baseline (speedup 1.0000x reference)
#include <cuda_runtime.h>
#include <cuda_bf16.h>
#include <cstdint>
#include <cstddef>

// Shapes fixed by dataset: B=2,H=16,S=4096,D=64, NSQ=NSK=2048. K & mask unused.
#define DD   64
#define BHN  32
#define NT   256
#define NSQ  2048
#define CH   64    // sample rows per block
#define PH1  66    // bf16 pitch, E/V transposed tiles (2-way STS, frag loads ok)
#define PH2  72    // bf16 pitch, Qsm + dotT tiles (conflict-free frag loads)
#define PVO  68    // f32 pitch, V tile + output staging tile (mult of 4 -> LDS.128 aligned)

// Global scratch: per-(b,h) GEMM1 accumulator, colsums, and completion counters.
__device__ float    g_M[BHN * DD * DD];
__device__ float    g_cs[BHN * DD];
__device__ unsigned g_cnt[BHN];

// smem layout (bytes):
//  A: 0     .. 9216   EsT [64][PH1] bf16 (8448) | later dotT [64][PH2] bf16 (9216)
//  B: 9216  .. 17664  VsT [64][PH1] bf16 (8448)
//     (A+B reused after GEMM2 as otile [64][PVO] f32 = 17408 <= 17664)
//  C: 17664 .. 26880  Qsm [64][PH2] bf16 (9216)
//  D: 26880 .. 44288  Vf32 [64][PVO] f32 (17408)
//  E: 44288 .. 44544  scs [64] f32
//  F: 44544 .. 45056  sidx [128] int
#define SM_A 0
#define SM_B 9216
#define SM_C 17664
#define SM_D 26880
#define SM_E 44288
#define SM_F 44544
#define SM_TOTAL 45056

__device__ __forceinline__ void mma_bf16(float* d,
    unsigned a0, unsigned a1, unsigned a2, unsigned a3, unsigned b0, unsigned b1) {
    asm("mma.sync.aligned.m16n8k16.row.col.f32.bf16.bf16.f32 "
        "{%0,%1,%2,%3}, {%4,%5,%6,%7}, {%8,%9}, {%0,%1,%2,%3};"
        : "+f"(d[0]), "+f"(d[1]), "+f"(d[2]), "+f"(d[3])
        : "r"(a0), "r"(a1), "r"(a2), "r"(a3), "r"(b0), "r"(b1));
}
__device__ __forceinline__ void red_add_v4(float* p, float a, float b, float c, float d) {
    asm volatile("red.global.add.v4.f32 [%0], {%1,%2,%3,%4};"
                 :: "l"(p), "f"(a), "f"(b), "f"(c), "f"(d) : "memory");
}
__device__ __forceinline__ void red_add_v2(float* p, float a, float b) {
    asm volatile("red.global.add.v2.f32 [%0], {%1,%2};"
                 :: "l"(p), "f"(a), "f"(b) : "memory");
}
__device__ __forceinline__ float warp_sum(float v) {
    #pragma unroll
    for (int o = 16; o; o >>= 1) v += __shfl_xor_sync(0xffffffffu, v, o);
    return v;
}
__device__ __forceinline__ unsigned ldu32(const __nv_bfloat16* p) {
    return *reinterpret_cast<const unsigned*>(p);
}

// Fused: zero out-slice + gather/softmax (tiles kept resident in smem) + GEMM1 ->
// red.add g_M -> release counter -> spin for bh completion -> dotT -> GEMM2 ->
// epilogue scatter (V from smem, out pre-zeroed by same-bh blocks).
__global__ void __launch_bounds__(NT, 4) k_fused(
    const float* __restrict__ Q, const float* __restrict__ V,
    const int* __restrict__ idxq, const int* __restrict__ idxk,
    float* __restrict__ out, float scaleA, float scaleB, int S)
{
    extern __shared__ char smraw[];
    __nv_bfloat16* EsT  = reinterpret_cast<__nv_bfloat16*>(smraw + SM_A);
    __nv_bfloat16* VsT  = reinterpret_cast<__nv_bfloat16*>(smraw + SM_B);
    __nv_bfloat16* Qsm  = reinterpret_cast<__nv_bfloat16*>(smraw + SM_C);
    float*         Vf   = reinterpret_cast<float*>(smraw + SM_D);
    float*         scs  = reinterpret_cast<float*>(smraw + SM_E);
    int*           sidx = reinterpret_cast<int*>(smraw + SM_F);
    __nv_bfloat16* dotT  = reinterpret_cast<__nv_bfloat16*>(smraw + SM_A); // after GEMM1
    float*         otile = reinterpret_cast<float*>(smraw + SM_A);         // after GEMM2

    const int bh   = blockIdx.y;
    const int j0   = blockIdx.x * CH;
    const int tid  = threadIdx.x;
    const int wid  = tid >> 5;
    const int lane = tid & 31;

    // Phase 0: zero this block's slice of out. Blocks (x,y) with x=0..31 cover
    // exactly bh=y's 262144 floats; scatter for bh y waits on g_cnt[y]==32,
    // which happens-after all 32 blocks' zeroing (membar before release).
    {
        const float4 z4 = make_float4(0.f, 0.f, 0.f, 0.f);
        float4* o4 = reinterpret_cast<float4*>(out)
                   + (size_t)(blockIdx.y * gridDim.x + blockIdx.x) * 2048;
        #pragma unroll
        for (int i = 0; i < 8; i++) o4[tid + i * NT] = z4;
    }

    const float* Qb = Q + (size_t)bh * S * DD;
    const float* Vb = V + (size_t)bh * S * DD;
    float* outb = out + (size_t)bh * S * DD;

    if (tid < CH)           sidx[tid] = idxq[j0 + tid];
    else if (tid < 2 * CH)  sidx[tid] = idxk[j0 + tid - CH];
    if (tid < DD) scs[tid] = 0.f;
    __syncthreads();

    // Phase 1: gather + softmax. Keeps Qsm (bf16), E=exp(Qsm) (bf16,T),
    // V (bf16,T and f32 row-major) all in smem. No max-subtraction needed.
    float csA = 0.f, csB = 0.f;
    for (int r = wid * 4; r < CH; r += 32) {
        float2 q[4], v[4];
        #pragma unroll
        for (int t = 0; t < 4; t++) {
            q[t] = reinterpret_cast<const float2*>(Qb + (size_t)sidx[r + t] * DD)[lane];
            v[t] = reinterpret_cast<const float2*>(Vb + (size_t)sidx[CH + r + t] * DD)[lane];
        }
        #pragma unroll
        for (int t = 0; t < 4; t++) {
            const int rr = r + t;
            float e0 = __expf(q[t].x), e1 = __expf(q[t].y);
            float inv = __fdividef(1.f, warp_sum(e0 + e1));
            float s0 = e0 * inv, s1 = e1 * inv;
            __nv_bfloat162 h2 = __floats2bfloat162_rn(s0, s1);
            *reinterpret_cast<unsigned*>(Qsm + rr * PH2 + 2 * lane)
                = *reinterpret_cast<unsigned*>(&h2);
            *reinterpret_cast<float2*>(Vf + rr * PVO + 2 * lane) = v[t];
            float E0 = __expf(s0), E1 = __expf(s1);
            EsT[(2 * lane) * PH1 + rr]     = __float2bfloat16(E0);
            EsT[(2 * lane + 1) * PH1 + rr] = __float2bfloat16(E1);
            VsT[(2 * lane) * PH1 + rr]     = __float2bfloat16(v[t].x);
            VsT[(2 * lane + 1) * PH1 + rr] = __float2bfloat16(v[t].y);
            csA += E0; csB += E1;
        }
    }
    atomicAdd(&scs[2 * lane],     csA);
    atomicAdd(&scs[2 * lane + 1], csB);
    __syncthreads();
    if (tid < DD) atomicAdd(&g_cs[bh * DD + tid], scs[tid]);

    // Phase 2: GEMM1 (bf16 m16n8k16): M=64(d) x N=64(e) x K=64(s) -> red to g_M.
    const int l4 = lane >> 2, lm = lane & 3;
    const int wm = wid & 1, wn = wid >> 1;
    {
        float D[2][2][4];
        #pragma unroll
        for (int mt = 0; mt < 2; mt++)
            #pragma unroll
            for (int nt = 0; nt < 2; nt++)
                #pragma unroll
                for (int u = 0; u < 4; u++) D[mt][nt][u] = 0.f;

        #pragma unroll
        for (int kc = 0; kc < CH; kc += 16) {
            unsigned a[2][4], b[2][2];
            #pragma unroll
            for (int mt = 0; mt < 2; mt++) {
                const __nv_bfloat16* ap = EsT + (wm * 32 + mt * 16 + l4) * PH1 + kc + 2 * lm;
                a[mt][0] = ldu32(ap);
                a[mt][1] = ldu32(ap + 8 * PH1);
                a[mt][2] = ldu32(ap + 8);
                a[mt][3] = ldu32(ap + 8 * PH1 + 8);
            }
            #pragma unroll
            for (int nt = 0; nt < 2; nt++) {
                const __nv_bfloat16* bp = VsT + (wn * 16 + nt * 8 + l4) * PH1 + kc + 2 * lm;
                b[nt][0] = ldu32(bp);
                b[nt][1] = ldu32(bp + 8);
            }
            #pragma unroll
            for (int mt = 0; mt < 2; mt++)
                #pragma unroll
                for (int nt = 0; nt < 2; nt++)
                    mma_bf16(D[mt][nt], a[mt][0], a[mt][1], a[mt][2], a[mt][3],
                             b[nt][0], b[nt][1]);
        }

        float* Mb = g_M + bh * DD * DD;
        #pragma unroll
        for (int mt = 0; mt < 2; mt++) {
            const int row = wm * 32 + mt * 16 + l4;
            #pragma unroll
            for (int nt = 0; nt < 2; nt++) {
                const int col = wn * 16 + nt * 8 + 2 * lm;
                red_add_v2(&Mb[row * DD + col],       D[mt][nt][0], D[mt][nt][1]);
                red_add_v2(&Mb[(row + 8) * DD + col], D[mt][nt][2], D[mt][nt][3]);
            }
        }
    }
    __syncthreads();   // all reds issued; EsT/VsT dead

    // Phase 3: publish + wait for all 32 blocks of this bh.
    if (tid == 0) {
        unsigned prev;
        asm volatile("membar.gl;" ::: "memory");
        asm volatile("atom.global.add.release.gpu.u32 %0, [%1], 1;"
                     : "=r"(prev) : "l"(&g_cnt[bh]) : "memory");
        unsigned c;
        do {
            asm volatile("ld.global.acquire.gpu.u32 %0, [%1];"
                         : "=r"(c) : "l"(&g_cnt[bh]) : "memory");
            if (c < 32) __nanosleep(64);
        } while (c < 32);
    }
    __syncthreads();

    // Phase 4: dotT[e][d] = bf16(M[d][e] / cs[d]) into region A.
    {
        const float* Mb = g_M + bh * DD * DD;
        const int d  = tid >> 2;
        const int e0 = (tid & 3) * 16;
        const float inv = __fdividef(1.f, g_cs[bh * DD + d]);
        const float4* mp = reinterpret_cast<const float4*>(Mb + d * DD + e0);
        #pragma unroll
        for (int u = 0; u < 4; u++) {
            float4 m = mp[u];
            dotT[(e0 + 4 * u)     * PH2 + d] = __float2bfloat16(m.x * inv);
            dotT[(e0 + 4 * u + 1) * PH2 + d] = __float2bfloat16(m.y * inv);
            dotT[(e0 + 4 * u + 2) * PH2 + d] = __float2bfloat16(m.z * inv);
            dotT[(e0 + 4 * u + 3) * PH2 + d] = __float2bfloat16(m.w * inv);
        }
    }
    __syncthreads();

    // Phase 5: GEMM2 (bf16): M=64(j) x N=64(e) x K=64(d). A = resident Qsm.
    float D2[2][2][4];
    #pragma unroll
    for (int mt = 0; mt < 2; mt++)
        #pragma unroll
        for (int nt = 0; nt < 2; nt++)
            #pragma unroll
            for (int u = 0; u < 4; u++) D2[mt][nt][u] = 0.f;

    #pragma unroll
    for (int kc = 0; kc < DD; kc += 16) {
        unsigned a[2][4], b[2][2];
        #pragma unroll
        for (int mt = 0; mt < 2; mt++) {
            const __nv_bfloat16* ap = Qsm + (wm * 32 + mt * 16 + l4) * PH2 + kc + 2 * lm;
            a[mt][0] = ldu32(ap);
            a[mt][1] = ldu32(ap + 8 * PH2);
            a[mt][2] = ldu32(ap + 8);
            a[mt][3] = ldu32(ap + 8 * PH2 + 8);
        }
        #pragma unroll
        for (int nt = 0; nt < 2; nt++) {
            const __nv_bfloat16* bp = dotT + (wn * 16 + nt * 8 + l4) * PH2 + kc + 2 * lm;
            b[nt][0] = ldu32(bp);
            b[nt][1] = ldu32(bp + 8);
        }
        #pragma unroll
        for (int mt = 0; mt < 2; mt++)
            #pragma unroll
            for (int nt = 0; nt < 2; nt++)
                mma_bf16(D2[mt][nt], a[mt][0], a[mt][1], a[mt][2], a[mt][3],
                         b[nt][0], b[nt][1]);
    }
    __syncthreads();   // dotT dead; reuse A+B as f32 otile

    // Phase 6: stage D fragments into f32 otile.
    #pragma unroll
    for (int mt = 0; mt < 2; mt++) {
        const int row = wm * 32 + mt * 16 + l4;
        #pragma unroll
        for (int nt = 0; nt < 2; nt++) {
            const int col = wn * 16 + nt * 8 + 2 * lm;
            *reinterpret_cast<float2*>(&otile[row * PVO + col])
                = make_float2(D2[mt][nt][0], D2[mt][nt][1]);
            *reinterpret_cast<float2*>(&otile[(row + 8) * PVO + col])
                = make_float2(D2[mt][nt][2], D2[mt][nt][3]);
        }
    }
    __syncthreads();

    // Phase 7: epilogue. Each thread owns 16 cols of one sample row; V from smem.
    {
        const int r  = tid >> 2;
        const int co = (tid & 3) * 16;
        const int qi = sidx[r];
        const float* ot = otile + r * PVO + co;
        const float* vr = Vf + r * PVO + co;
        float* op = outb + (size_t)qi * DD + co;
        #pragma unroll
        for (int u = 0; u < 4; u++) {
            float4 v = *reinterpret_cast<const float4*>(vr + 4 * u);
            red_add_v4(op + 4 * u,
                       fmaf(scaleA, ot[4 * u],     scaleB * v.x),
                       fmaf(scaleA, ot[4 * u + 1], scaleB * v.y),
                       fmaf(scaleA, ot[4 * u + 2], scaleB * v.z),
                       fmaf(scaleA, ot[4 * u + 3], scaleB * v.w));
        }
    }
}

extern "C" void kernel_launch(void* const* d_in, const int* in_sizes, int n_in,
                              void* d_out, int out_size)
{
    const float* Q    = (const float*)d_in[0];
    const float* V    = (const float*)d_in[2];
    const int*   idxq = (const int*)d_in[4];
    const int*   idxk = (const int*)d_in[5];
    float* out = (float*)d_out;

    const int nsq = in_sizes[4];
    const int nsk = in_sizes[5];
    const int S   = in_sizes[0] / (BHN * DD);
    const float scaleA = (float)S * (float)S / ((float)nsq * (float)nsk);
    const float scaleB = (float)S / (float)nsk;

    void* mptr = nullptr; cudaGetSymbolAddress(&mptr, g_M);
    void* cptr = nullptr; cudaGetSymbolAddress(&cptr, g_cs);
    void* nptr = nullptr; cudaGetSymbolAddress(&nptr, g_cnt);
    cudaMemsetAsync(mptr, 0, sizeof(float) * BHN * DD * DD);
    cudaMemsetAsync(cptr, 0, sizeof(float) * BHN * DD);
    cudaMemsetAsync(nptr, 0, sizeof(unsigned) * BHN);

    cudaFuncSetAttribute(k_fused, cudaFuncAttributeMaxDynamicSharedMemorySize, SM_TOTAL);

    dim3 g(nsq / CH, BHN);   // 32 x 32 = 1024 blocks
    k_fused<<<g, NT, SM_TOTAL>>>(Q, V, idxq, idxk, out, scaleA, scaleB, S);
}

// round 14
// speedup vs baseline: 1.0783x; 1.0783x over previous
#include <cuda_runtime.h>
#include <cuda_bf16.h>
#include <cstdint>
#include <cstddef>

// Shapes fixed by dataset: B=2,H=16,S=4096,D=64, NSQ=NSK=2048. K & mask unused.
#define DD   64
#define BHN  32
#define NT   256
#define NSQ  2048
#define CH   64    // sample rows per block
#define PH1  66    // bf16 pitch, E/V transposed tiles (2-way STS, frag loads ok)
#define PH2  72    // bf16 pitch, Qsm + dotT tiles (conflict-free frag loads)
#define PVO  68    // f32 pitch, V / M-staging / output tiles (mult of 4 -> LDS.128 aligned)

// Single contiguous global scratch: g_M | g_cs | g_cnt  (one memset per launch).
#define G_M_OFF   0
#define G_CS_OFF  (BHN * DD * DD)
#define G_CNT_OFF (G_CS_OFF + BHN * DD)
#define G_TOTAL   (G_CNT_OFF + BHN)
__device__ float g_scratch[G_TOTAL];

// smem layout (bytes):
//  A: 0     .. 9216   EsT [64][PH1] bf16 (8448)
//  B: 9216  .. 17664  VsT [64][PH1] bf16 (8448)
//     A+B reused: mtile [64][PVO] f32 (17408) after GEMM1,
//                 dotT  [64][PH2] bf16 (9216) after spin,
//                 otile [64][PVO] f32 (17408) after GEMM2
//  C: 17664 .. 26880  Qsm [64][PH2] bf16 (9216)
//  D: 26880 .. 44288  Vf32 [64][PVO] f32 (17408)
//  E: 44288 .. 44544  scs [64] f32
//  F: 44544 .. 45056  sidx [128] int
#define SM_A 0
#define SM_B 9216
#define SM_C 17664
#define SM_D 26880
#define SM_E 44288
#define SM_F 44544
#define SM_TOTAL 45056

__device__ __forceinline__ void mma_bf16(float* d,
    unsigned a0, unsigned a1, unsigned a2, unsigned a3, unsigned b0, unsigned b1) {
    asm("mma.sync.aligned.m16n8k16.row.col.f32.bf16.bf16.f32 "
        "{%0,%1,%2,%3}, {%4,%5,%6,%7}, {%8,%9}, {%0,%1,%2,%3};"
        : "+f"(d[0]), "+f"(d[1]), "+f"(d[2]), "+f"(d[3])
        : "r"(a0), "r"(a1), "r"(a2), "r"(a3), "r"(b0), "r"(b1));
}
__device__ __forceinline__ void red_add_v4(float* p, float a, float b, float c, float d) {
    asm volatile("red.global.add.v4.f32 [%0], {%1,%2,%3,%4};"
                 :: "l"(p), "f"(a), "f"(b), "f"(c), "f"(d) : "memory");
}
__device__ __forceinline__ float warp_sum(float v) {
    #pragma unroll
    for (int o = 16; o; o >>= 1) v += __shfl_xor_sync(0xffffffffu, v, o);
    return v;
}
__device__ __forceinline__ unsigned ldu32(const __nv_bfloat16* p) {
    return *reinterpret_cast<const unsigned*>(p);
}

// Fused: zero out-slice + gather/softmax (tiles resident in smem) + GEMM1 ->
// staged red.add.v4 to g_M -> release counter -> spin for bh completion ->
// dotT -> GEMM2 -> epilogue scatter (V from smem, out pre-zeroed by same-bh blocks).
__global__ void __launch_bounds__(NT, 4) k_fused(
    const float* __restrict__ Q, const float* __restrict__ V,
    const int* __restrict__ idxq, const int* __restrict__ idxk,
    float* __restrict__ out, float scaleA, float scaleB, int S)
{
    extern __shared__ char smraw[];
    __nv_bfloat16* EsT  = reinterpret_cast<__nv_bfloat16*>(smraw + SM_A);
    __nv_bfloat16* VsT  = reinterpret_cast<__nv_bfloat16*>(smraw + SM_B);
    __nv_bfloat16* Qsm  = reinterpret_cast<__nv_bfloat16*>(smraw + SM_C);
    float*         Vf   = reinterpret_cast<float*>(smraw + SM_D);
    float*         scs  = reinterpret_cast<float*>(smraw + SM_E);
    int*           sidx = reinterpret_cast<int*>(smraw + SM_F);
    float*         mtile = reinterpret_cast<float*>(smraw + SM_A);         // after GEMM1
    __nv_bfloat16* dotT  = reinterpret_cast<__nv_bfloat16*>(smraw + SM_A); // after spin
    float*         otile = reinterpret_cast<float*>(smraw + SM_A);         // after GEMM2

    const int bh   = blockIdx.y;
    const int j0   = blockIdx.x * CH;
    const int tid  = threadIdx.x;
    const int wid  = tid >> 5;
    const int lane = tid & 31;

    float*    g_M   = g_scratch + G_M_OFF;
    float*    g_cs  = g_scratch + G_CS_OFF;
    unsigned* g_cnt = reinterpret_cast<unsigned*>(g_scratch + G_CNT_OFF);

    // Phase 0: zero this block's slice of out (32 blocks per bh cover its region;
    // scatter for bh waits on g_cnt[bh]==32 which happens-after all zeroing).
    {
        const float4 z4 = make_float4(0.f, 0.f, 0.f, 0.f);
        float4* o4 = reinterpret_cast<float4*>(out)
                   + (size_t)(blockIdx.y * gridDim.x + blockIdx.x) * 2048;
        #pragma unroll
        for (int i = 0; i < 8; i++) o4[tid + i * NT] = z4;
    }

    const float* Qb = Q + (size_t)bh * S * DD;
    const float* Vb = V + (size_t)bh * S * DD;
    float* outb = out + (size_t)bh * S * DD;

    if (tid < CH)           sidx[tid] = idxq[j0 + tid];
    else if (tid < 2 * CH)  sidx[tid] = idxk[j0 + tid - CH];
    if (tid < DD) scs[tid] = 0.f;
    __syncthreads();

    // Phase 1: gather + softmax. Keeps Qsm (bf16), E=exp(Qsm) (bf16,T),
    // V (bf16,T and f32 row-major) all in smem. No max-subtraction needed.
    float csA = 0.f, csB = 0.f;
    for (int r = wid * 4; r < CH; r += 32) {
        float2 q[4], v[4];
        #pragma unroll
        for (int t = 0; t < 4; t++) {
            q[t] = reinterpret_cast<const float2*>(Qb + (size_t)sidx[r + t] * DD)[lane];
            v[t] = reinterpret_cast<const float2*>(Vb + (size_t)sidx[CH + r + t] * DD)[lane];
        }
        #pragma unroll
        for (int t = 0; t < 4; t++) {
            const int rr = r + t;
            float e0 = __expf(q[t].x), e1 = __expf(q[t].y);
            float inv = __fdividef(1.f, warp_sum(e0 + e1));
            float s0 = e0 * inv, s1 = e1 * inv;
            __nv_bfloat162 h2 = __floats2bfloat162_rn(s0, s1);
            *reinterpret_cast<unsigned*>(Qsm + rr * PH2 + 2 * lane)
                = *reinterpret_cast<unsigned*>(&h2);
            *reinterpret_cast<float2*>(Vf + rr * PVO + 2 * lane) = v[t];
            float E0 = __expf(s0), E1 = __expf(s1);
            EsT[(2 * lane) * PH1 + rr]     = __float2bfloat16(E0);
            EsT[(2 * lane + 1) * PH1 + rr] = __float2bfloat16(E1);
            VsT[(2 * lane) * PH1 + rr]     = __float2bfloat16(v[t].x);
            VsT[(2 * lane + 1) * PH1 + rr] = __float2bfloat16(v[t].y);
            csA += E0; csB += E1;
        }
    }
    atomicAdd(&scs[2 * lane],     csA);
    atomicAdd(&scs[2 * lane + 1], csB);
    __syncthreads();
    if (tid < DD) atomicAdd(&g_cs[bh * DD + tid], scs[tid]);

    // Phase 2: GEMM1 (bf16 m16n8k16): M=64(d) x N=64(e) x K=64(s).
    const int l4 = lane >> 2, lm = lane & 3;
    const int wm = wid & 1, wn = wid >> 1;
    {
        float D[2][2][4];
        #pragma unroll
        for (int mt = 0; mt < 2; mt++)
            #pragma unroll
            for (int nt = 0; nt < 2; nt++)
                #pragma unroll
                for (int u = 0; u < 4; u++) D[mt][nt][u] = 0.f;

        #pragma unroll
        for (int kc = 0; kc < CH; kc += 16) {
            unsigned a[2][4], b[2][2];
            #pragma unroll
            for (int mt = 0; mt < 2; mt++) {
                const __nv_bfloat16* ap = EsT + (wm * 32 + mt * 16 + l4) * PH1 + kc + 2 * lm;
                a[mt][0] = ldu32(ap);
                a[mt][1] = ldu32(ap + 8 * PH1);
                a[mt][2] = ldu32(ap + 8);
                a[mt][3] = ldu32(ap + 8 * PH1 + 8);
            }
            #pragma unroll
            for (int nt = 0; nt < 2; nt++) {
                const __nv_bfloat16* bp = VsT + (wn * 16 + nt * 8 + l4) * PH1 + kc + 2 * lm;
                b[nt][0] = ldu32(bp);
                b[nt][1] = ldu32(bp + 8);
            }
            #pragma unroll
            for (int mt = 0; mt < 2; mt++)
                #pragma unroll
                for (int nt = 0; nt < 2; nt++)
                    mma_bf16(D[mt][nt], a[mt][0], a[mt][1], a[mt][2], a[mt][3],
                             b[nt][0], b[nt][1]);
        }
        __syncthreads();   // all EsT/VsT reads done before overwrite as mtile

        // Stage D fragments into f32 mtile, then coalesced red.add.v4 to g_M
        // (4 v4 lane-ops/thread instead of 8 scattered v2 -> halves REDG load).
        #pragma unroll
        for (int mt = 0; mt < 2; mt++) {
            const int row = wm * 32 + mt * 16 + l4;
            #pragma unroll
            for (int nt = 0; nt < 2; nt++) {
                const int col = wn * 16 + nt * 8 + 2 * lm;
                *reinterpret_cast<float2*>(&mtile[row * PVO + col])
                    = make_float2(D[mt][nt][0], D[mt][nt][1]);
                *reinterpret_cast<float2*>(&mtile[(row + 8) * PVO + col])
                    = make_float2(D[mt][nt][2], D[mt][nt][3]);
            }
        }
        __syncthreads();
        {
            const int rr = tid >> 2;
            const int cc = (tid & 3) * 16;
            float* Mb = g_M + bh * DD * DD;
            const float* mp = mtile + rr * PVO + cc;
            #pragma unroll
            for (int u = 0; u < 4; u++) {
                float4 m = *reinterpret_cast<const float4*>(mp + 4 * u);
                red_add_v4(&Mb[rr * DD + cc + 4 * u], m.x, m.y, m.z, m.w);
            }
        }
    }

    // Phase 3: publish + wait for all 32 blocks of this bh.
    __syncthreads();
    if (tid == 0) {
        unsigned prev;
        asm volatile("membar.gl;" ::: "memory");
        asm volatile("atom.global.add.release.gpu.u32 %0, [%1], 1;"
                     : "=r"(prev) : "l"(&g_cnt[bh]) : "memory");
        unsigned c;
        do {
            asm volatile("ld.global.acquire.gpu.u32 %0, [%1];"
                         : "=r"(c) : "l"(&g_cnt[bh]) : "memory");
            if (c < 32) __nanosleep(64);
        } while (c < 32);
    }
    __syncthreads();

    // Phase 4: dotT[e][d] = bf16(M[d][e] / cs[d]) into region A (mtile dead).
    {
        const float* Mb = g_M + bh * DD * DD;
        const int d  = tid >> 2;
        const int e0 = (tid & 3) * 16;
        const float inv = __fdividef(1.f, g_cs[bh * DD + d]);
        const float4* mp = reinterpret_cast<const float4*>(Mb + d * DD + e0);
        #pragma unroll
        for (int u = 0; u < 4; u++) {
            float4 m = mp[u];
            dotT[(e0 + 4 * u)     * PH2 + d] = __float2bfloat16(m.x * inv);
            dotT[(e0 + 4 * u + 1) * PH2 + d] = __float2bfloat16(m.y * inv);
            dotT[(e0 + 4 * u + 2) * PH2 + d] = __float2bfloat16(m.z * inv);
            dotT[(e0 + 4 * u + 3) * PH2 + d] = __float2bfloat16(m.w * inv);
        }
    }
    __syncthreads();

    // Phase 5: GEMM2 (bf16): M=64(j) x N=64(e) x K=64(d). A = resident Qsm.
    float D2[2][2][4];
    #pragma unroll
    for (int mt = 0; mt < 2; mt++)
        #pragma unroll
        for (int nt = 0; nt < 2; nt++)
            #pragma unroll
            for (int u = 0; u < 4; u++) D2[mt][nt][u] = 0.f;

    #pragma unroll
    for (int kc = 0; kc < DD; kc += 16) {
        unsigned a[2][4], b[2][2];
        #pragma unroll
        for (int mt = 0; mt < 2; mt++) {
            const __nv_bfloat16* ap = Qsm + (wm * 32 + mt * 16 + l4) * PH2 + kc + 2 * lm;
            a[mt][0] = ldu32(ap);
            a[mt][1] = ldu32(ap + 8 * PH2);
            a[mt][2] = ldu32(ap + 8);
            a[mt][3] = ldu32(ap + 8 * PH2 + 8);
        }
        #pragma unroll
        for (int nt = 0; nt < 2; nt++) {
            const __nv_bfloat16* bp = dotT + (wn * 16 + nt * 8 + l4) * PH2 + kc + 2 * lm;
            b[nt][0] = ldu32(bp);
            b[nt][1] = ldu32(bp + 8);
        }
        #pragma unroll
        for (int mt = 0; mt < 2; mt++)
            #pragma unroll
            for (int nt = 0; nt < 2; nt++)
                mma_bf16(D2[mt][nt], a[mt][0], a[mt][1], a[mt][2], a[mt][3],
                         b[nt][0], b[nt][1]);
    }
    __syncthreads();   // dotT dead; reuse A+B as f32 otile

    // Phase 6: stage D2 fragments into f32 otile.
    #pragma unroll
    for (int mt = 0; mt < 2; mt++) {
        const int row = wm * 32 + mt * 16 + l4;
        #pragma unroll
        for (int nt = 0; nt < 2; nt++) {
            const int col = wn * 16 + nt * 8 + 2 * lm;
            *reinterpret_cast<float2*>(&otile[row * PVO + col])
                = make_float2(D2[mt][nt][0], D2[mt][nt][1]);
            *reinterpret_cast<float2*>(&otile[(row + 8) * PVO + col])
                = make_float2(D2[mt][nt][2], D2[mt][nt][3]);
        }
    }
    __syncthreads();

    // Phase 7: epilogue. Each thread owns 16 cols of one sample row; V from smem.
    {
        const int r  = tid >> 2;
        const int co = (tid & 3) * 16;
        const int qi = sidx[r];
        const float* ot = otile + r * PVO + co;
        const float* vr = Vf + r * PVO + co;
        float* op = outb + (size_t)qi * DD + co;
        #pragma unroll
        for (int u = 0; u < 4; u++) {
            float4 v = *reinterpret_cast<const float4*>(vr + 4 * u);
            red_add_v4(op + 4 * u,
                       fmaf(scaleA, ot[4 * u],     scaleB * v.x),
                       fmaf(scaleA, ot[4 * u + 1], scaleB * v.y),
                       fmaf(scaleA, ot[4 * u + 2], scaleB * v.z),
                       fmaf(scaleA, ot[4 * u + 3], scaleB * v.w));
        }
    }
}

extern "C" void kernel_launch(void* const* d_in, const int* in_sizes, int n_in,
                              void* d_out, int out_size)
{
    const float* Q    = (const float*)d_in[0];
    const float* V    = (const float*)d_in[2];
    const int*   idxq = (const int*)d_in[4];
    const int*   idxk = (const int*)d_in[5];
    float* out = (float*)d_out;

    const int nsq = in_sizes[4];
    const int nsk = in_sizes[5];
    const int S   = in_sizes[0] / (BHN * DD);
    const float scaleA = (float)S * (float)S / ((float)nsq * (float)nsk);
    const float scaleB = (float)S / (float)nsk;

    void* sptr = nullptr; cudaGetSymbolAddress(&sptr, g_scratch);
    cudaMemsetAsync(sptr, 0, sizeof(float) * G_TOTAL);   // single scratch memset

    cudaFuncSetAttribute(k_fused, cudaFuncAttributeMaxDynamicSharedMemorySize, SM_TOTAL);

    dim3 g(nsq / CH, BHN);   // 32 x 32 = 1024 blocks
    k_fused<<<g, NT, SM_TOTAL>>>(Q, V, idxq, idxk, out, scaleA, scaleB, S);
}

// round 15
// speedup vs baseline: 1.1340x; 1.0517x over previous
#include <cuda_runtime.h>
#include <cuda_bf16.h>
#include <cstdint>
#include <cstddef>

// Shapes fixed by dataset: B=2,H=16,S=4096,D=64, NSQ=NSK=2048. K & mask unused.
#define DD   64
#define BHN  32
#define NT   256
#define NSQ  2048
#define CH   64    // sample rows per block
#define PH1  66    // bf16 pitch, E/V transposed tiles (2-way STS, frag loads ok)
#define PH2  72    // bf16 pitch, Qsm + dotT tiles (conflict-free frag loads)
#define PVO  68    // f32 pitch, V tile + output staging tile (mult of 4 -> LDS.128 aligned)

// Single contiguous global scratch: g_M | g_cs | g_cnt  (one memset per launch).
#define G_M_OFF   0
#define G_CS_OFF  (BHN * DD * DD)
#define G_CNT_OFF (G_CS_OFF + BHN * DD)
#define G_TOTAL   (G_CNT_OFF + BHN)
__device__ float g_scratch[G_TOTAL];

// smem layout (bytes):
//  A: 0     .. 9216   EsT [64][PH1] bf16 (8448) | later dotT [64][PH2] bf16 (9216)
//  B: 9216  .. 17664  VsT [64][PH1] bf16 (8448)
//     (A+B reused after GEMM2 as otile [64][PVO] f32 = 17408 <= 17664)
//  C: 17664 .. 26880  Qsm [64][PH2] bf16 (9216)
//  D: 26880 .. 44288  Vf32 [64][PVO] f32 (17408)
//  E: 44288 .. 44544  scs [64] f32
//  F: 44544 .. 45056  sidx [128] int
#define SM_A 0
#define SM_B 9216
#define SM_C 17664
#define SM_D 26880
#define SM_E 44288
#define SM_F 44544
#define SM_TOTAL 45056

__device__ __forceinline__ void mma_bf16(float* d,
    unsigned a0, unsigned a1, unsigned a2, unsigned a3, unsigned b0, unsigned b1) {
    asm("mma.sync.aligned.m16n8k16.row.col.f32.bf16.bf16.f32 "
        "{%0,%1,%2,%3}, {%4,%5,%6,%7}, {%8,%9}, {%0,%1,%2,%3};"
        : "+f"(d[0]), "+f"(d[1]), "+f"(d[2]), "+f"(d[3])
        : "r"(a0), "r"(a1), "r"(a2), "r"(a3), "r"(b0), "r"(b1));
}
__device__ __forceinline__ void red_add_v4(float* p, float a, float b, float c, float d) {
    asm volatile("red.global.add.v4.f32 [%0], {%1,%2,%3,%4};"
                 :: "l"(p), "f"(a), "f"(b), "f"(c), "f"(d) : "memory");
}
__device__ __forceinline__ void red_add_v2(float* p, float a, float b) {
    asm volatile("red.global.add.v2.f32 [%0], {%1,%2};"
                 :: "l"(p), "f"(a), "f"(b) : "memory");
}
__device__ __forceinline__ float warp_sum(float v) {
    #pragma unroll
    for (int o = 16; o; o >>= 1) v += __shfl_xor_sync(0xffffffffu, v, o);
    return v;
}
__device__ __forceinline__ unsigned ldu32(const __nv_bfloat16* p) {
    return *reinterpret_cast<const unsigned*>(p);
}

// Fused: zero out-slice + gather/softmax (tiles kept resident in smem) + GEMM1 ->
// red.add g_M -> release counter -> spin for bh completion -> dotT -> GEMM2 ->
// epilogue scatter (V from smem, out pre-zeroed by same-bh blocks).
__global__ void __launch_bounds__(NT, 4) k_fused(
    const float* __restrict__ Q, const float* __restrict__ V,
    const int* __restrict__ idxq, const int* __restrict__ idxk,
    float* __restrict__ out, float scaleA, float scaleB, int S)
{
    extern __shared__ char smraw[];
    __nv_bfloat16* EsT  = reinterpret_cast<__nv_bfloat16*>(smraw + SM_A);
    __nv_bfloat16* VsT  = reinterpret_cast<__nv_bfloat16*>(smraw + SM_B);
    __nv_bfloat16* Qsm  = reinterpret_cast<__nv_bfloat16*>(smraw + SM_C);
    float*         Vf   = reinterpret_cast<float*>(smraw + SM_D);
    float*         scs  = reinterpret_cast<float*>(smraw + SM_E);
    int*           sidx = reinterpret_cast<int*>(smraw + SM_F);
    __nv_bfloat16* dotT  = reinterpret_cast<__nv_bfloat16*>(smraw + SM_A); // after GEMM1
    float*         otile = reinterpret_cast<float*>(smraw + SM_A);         // after GEMM2

    const int bh   = blockIdx.y;
    const int j0   = blockIdx.x * CH;
    const int tid  = threadIdx.x;
    const int wid  = tid >> 5;
    const int lane = tid & 31;

    float*    g_M   = g_scratch + G_M_OFF;
    float*    g_cs  = g_scratch + G_CS_OFF;
    unsigned* g_cnt = reinterpret_cast<unsigned*>(g_scratch + G_CNT_OFF);

    // Phase 0: zero this block's slice of out. Blocks (x,y) with x=0..31 cover
    // exactly bh=y's 262144 floats; scatter for bh y waits on g_cnt[y]==32,
    // which happens-after all 32 blocks' zeroing (membar before release).
    {
        const float4 z4 = make_float4(0.f, 0.f, 0.f, 0.f);
        float4* o4 = reinterpret_cast<float4*>(out)
                   + (size_t)(blockIdx.y * gridDim.x + blockIdx.x) * 2048;
        #pragma unroll
        for (int i = 0; i < 8; i++) o4[tid + i * NT] = z4;
    }

    const float* Qb = Q + (size_t)bh * S * DD;
    const float* Vb = V + (size_t)bh * S * DD;
    float* outb = out + (size_t)bh * S * DD;

    if (tid < CH)           sidx[tid] = idxq[j0 + tid];
    else if (tid < 2 * CH)  sidx[tid] = idxk[j0 + tid - CH];
    if (tid < DD) scs[tid] = 0.f;
    __syncthreads();

    // Phase 1: gather + softmax. Keeps Qsm (bf16), E=exp(Qsm) (bf16,T),
    // V (bf16,T and f32 row-major) all in smem. No max-subtraction needed.
    float csA = 0.f, csB = 0.f;
    for (int r = wid * 4; r < CH; r += 32) {
        float2 q[4], v[4];
        #pragma unroll
        for (int t = 0; t < 4; t++) {
            q[t] = reinterpret_cast<const float2*>(Qb + (size_t)sidx[r + t] * DD)[lane];
            v[t] = reinterpret_cast<const float2*>(Vb + (size_t)sidx[CH + r + t] * DD)[lane];
        }
        #pragma unroll
        for (int t = 0; t < 4; t++) {
            const int rr = r + t;
            float e0 = __expf(q[t].x), e1 = __expf(q[t].y);
            float inv = __fdividef(1.f, warp_sum(e0 + e1));
            float s0 = e0 * inv, s1 = e1 * inv;
            __nv_bfloat162 h2 = __floats2bfloat162_rn(s0, s1);
            *reinterpret_cast<unsigned*>(Qsm + rr * PH2 + 2 * lane)
                = *reinterpret_cast<unsigned*>(&h2);
            *reinterpret_cast<float2*>(Vf + rr * PVO + 2 * lane) = v[t];
            float E0 = __expf(s0), E1 = __expf(s1);
            EsT[(2 * lane) * PH1 + rr]     = __float2bfloat16(E0);
            EsT[(2 * lane + 1) * PH1 + rr] = __float2bfloat16(E1);
            VsT[(2 * lane) * PH1 + rr]     = __float2bfloat16(v[t].x);
            VsT[(2 * lane + 1) * PH1 + rr] = __float2bfloat16(v[t].y);
            csA += E0; csB += E1;
        }
    }
    atomicAdd(&scs[2 * lane],     csA);
    atomicAdd(&scs[2 * lane + 1], csB);
    __syncthreads();
    if (tid < DD) atomicAdd(&g_cs[bh * DD + tid], scs[tid]);

    // Phase 2: GEMM1 (bf16 m16n8k16): M=64(d) x N=64(e) x K=64(s) -> red to g_M.
    const int l4 = lane >> 2, lm = lane & 3;
    const int wm = wid & 1, wn = wid >> 1;
    {
        float D[2][2][4];
        #pragma unroll
        for (int mt = 0; mt < 2; mt++)
            #pragma unroll
            for (int nt = 0; nt < 2; nt++)
                #pragma unroll
                for (int u = 0; u < 4; u++) D[mt][nt][u] = 0.f;

        #pragma unroll
        for (int kc = 0; kc < CH; kc += 16) {
            unsigned a[2][4], b[2][2];
            #pragma unroll
            for (int mt = 0; mt < 2; mt++) {
                const __nv_bfloat16* ap = EsT + (wm * 32 + mt * 16 + l4) * PH1 + kc + 2 * lm;
                a[mt][0] = ldu32(ap);
                a[mt][1] = ldu32(ap + 8 * PH1);
                a[mt][2] = ldu32(ap + 8);
                a[mt][3] = ldu32(ap + 8 * PH1 + 8);
            }
            #pragma unroll
            for (int nt = 0; nt < 2; nt++) {
                const __nv_bfloat16* bp = VsT + (wn * 16 + nt * 8 + l4) * PH1 + kc + 2 * lm;
                b[nt][0] = ldu32(bp);
                b[nt][1] = ldu32(bp + 8);
            }
            #pragma unroll
            for (int mt = 0; mt < 2; mt++)
                #pragma unroll
                for (int nt = 0; nt < 2; nt++)
                    mma_bf16(D[mt][nt], a[mt][0], a[mt][1], a[mt][2], a[mt][3],
                             b[nt][0], b[nt][1]);
        }

        float* Mb = g_M + bh * DD * DD;
        #pragma unroll
        for (int mt = 0; mt < 2; mt++) {
            const int row = wm * 32 + mt * 16 + l4;
            #pragma unroll
            for (int nt = 0; nt < 2; nt++) {
                const int col = wn * 16 + nt * 8 + 2 * lm;
                red_add_v2(&Mb[row * DD + col],       D[mt][nt][0], D[mt][nt][1]);
                red_add_v2(&Mb[(row + 8) * DD + col], D[mt][nt][2], D[mt][nt][3]);
            }
        }
    }
    __syncthreads();   // all reds issued; EsT/VsT dead

    // Phase 3: publish + wait for all 32 blocks of this bh.
    if (tid == 0) {
        unsigned prev;
        asm volatile("membar.gl;" ::: "memory");
        asm volatile("atom.global.add.release.gpu.u32 %0, [%1], 1;"
                     : "=r"(prev) : "l"(&g_cnt[bh]) : "memory");
        unsigned c;
        do {
            asm volatile("ld.global.acquire.gpu.u32 %0, [%1];"
                         : "=r"(c) : "l"(&g_cnt[bh]) : "memory");
            if (c < 32) __nanosleep(64);
        } while (c < 32);
    }
    __syncthreads();

    // Phase 4: dotT[e][d] = bf16(M[d][e] / cs[d]) into region A.
    {
        const float* Mb = g_M + bh * DD * DD;
        const int d  = tid >> 2;
        const int e0 = (tid & 3) * 16;
        const float inv = __fdividef(1.f, g_cs[bh * DD + d]);
        const float4* mp = reinterpret_cast<const float4*>(Mb + d * DD + e0);
        #pragma unroll
        for (int u = 0; u < 4; u++) {
            float4 m = mp[u];
            dotT[(e0 + 4 * u)     * PH2 + d] = __float2bfloat16(m.x * inv);
            dotT[(e0 + 4 * u + 1) * PH2 + d] = __float2bfloat16(m.y * inv);
            dotT[(e0 + 4 * u + 2) * PH2 + d] = __float2bfloat16(m.z * inv);
            dotT[(e0 + 4 * u + 3) * PH2 + d] = __float2bfloat16(m.w * inv);
        }
    }
    __syncthreads();

    // Phase 5: GEMM2 (bf16): M=64(j) x N=64(e) x K=64(d). A = resident Qsm.
    float D2[2][2][4];
    #pragma unroll
    for (int mt = 0; mt < 2; mt++)
        #pragma unroll
        for (int nt = 0; nt < 2; nt++)
            #pragma unroll
            for (int u = 0; u < 4; u++) D2[mt][nt][u] = 0.f;

    #pragma unroll
    for (int kc = 0; kc < DD; kc += 16) {
        unsigned a[2][4], b[2][2];
        #pragma unroll
        for (int mt = 0; mt < 2; mt++) {
            const __nv_bfloat16* ap = Qsm + (wm * 32 + mt * 16 + l4) * PH2 + kc + 2 * lm;
            a[mt][0] = ldu32(ap);
            a[mt][1] = ldu32(ap + 8 * PH2);
            a[mt][2] = ldu32(ap + 8);
            a[mt][3] = ldu32(ap + 8 * PH2 + 8);
        }
        #pragma unroll
        for (int nt = 0; nt < 2; nt++) {
            const __nv_bfloat16* bp = dotT + (wn * 16 + nt * 8 + l4) * PH2 + kc + 2 * lm;
            b[nt][0] = ldu32(bp);
            b[nt][1] = ldu32(bp + 8);
        }
        #pragma unroll
        for (int mt = 0; mt < 2; mt++)
            #pragma unroll
            for (int nt = 0; nt < 2; nt++)
                mma_bf16(D2[mt][nt], a[mt][0], a[mt][1], a[mt][2], a[mt][3],
                         b[nt][0], b[nt][1]);
    }
    __syncthreads();   // dotT dead; reuse A+B as f32 otile

    // Phase 6: stage D2 fragments into f32 otile.
    #pragma unroll
    for (int mt = 0; mt < 2; mt++) {
        const int row = wm * 32 + mt * 16 + l4;
        #pragma unroll
        for (int nt = 0; nt < 2; nt++) {
            const int col = wn * 16 + nt * 8 + 2 * lm;
            *reinterpret_cast<float2*>(&otile[row * PVO + col])
                = make_float2(D2[mt][nt][0], D2[mt][nt][1]);
            *reinterpret_cast<float2*>(&otile[(row + 8) * PVO + col])
                = make_float2(D2[mt][nt][2], D2[mt][nt][3]);
        }
    }
    __syncthreads();

    // Phase 7: epilogue. Each thread owns 16 cols of one sample row; V from smem.
    {
        const int r  = tid >> 2;
        const int co = (tid & 3) * 16;
        const int qi = sidx[r];
        const float* ot = otile + r * PVO + co;
        const float* vr = Vf + r * PVO + co;
        float* op = outb + (size_t)qi * DD + co;
        #pragma unroll
        for (int u = 0; u < 4; u++) {
            float4 v = *reinterpret_cast<const float4*>(vr + 4 * u);
            red_add_v4(op + 4 * u,
                       fmaf(scaleA, ot[4 * u],     scaleB * v.x),
                       fmaf(scaleA, ot[4 * u + 1], scaleB * v.y),
                       fmaf(scaleA, ot[4 * u + 2], scaleB * v.z),
                       fmaf(scaleA, ot[4 * u + 3], scaleB * v.w));
        }
    }
}

extern "C" void kernel_launch(void* const* d_in, const int* in_sizes, int n_in,
                              void* d_out, int out_size)
{
    const float* Q    = (const float*)d_in[0];
    const float* V    = (const float*)d_in[2];
    const int*   idxq = (const int*)d_in[4];
    const int*   idxk = (const int*)d_in[5];
    float* out = (float*)d_out;

    const int nsq = in_sizes[4];
    const int nsk = in_sizes[5];
    const int S   = in_sizes[0] / (BHN * DD);
    const float scaleA = (float)S * (float)S / ((float)nsq * (float)nsk);
    const float scaleB = (float)S / (float)nsk;

    void* sptr = nullptr; cudaGetSymbolAddress(&sptr, g_scratch);
    cudaMemsetAsync(sptr, 0, sizeof(float) * G_TOTAL);   // single scratch memset

    cudaFuncSetAttribute(k_fused, cudaFuncAttributeMaxDynamicSharedMemorySize, SM_TOTAL);

    dim3 g(nsq / CH, BHN);   // 32 x 32 = 1024 blocks
    k_fused<<<g, NT, SM_TOTAL>>>(Q, V, idxq, idxk, out, scaleA, scaleB, S);
}

// round 16
// speedup vs baseline: 1.1404x; 1.0057x over previous
#include <cuda_runtime.h>
#include <cuda_bf16.h>
#include <cstdint>
#include <cstddef>

// Shapes fixed by dataset: B=2,H=16,S=4096,D=64, NSQ=NSK=2048. K & mask unused.
#define DD   64
#define BHN  32
#define NT   256
#define NSQ  2048
#define CH   64    // sample rows per block
#define PH1  66    // bf16 pitch, E/V transposed tiles (2-way STS, frag loads ok)
#define PH2  72    // bf16 pitch, Qsm + dotT tiles (conflict-free frag loads)
#define PVO  68    // f32 pitch, V tile + output staging tile (mult of 4 -> LDS.128 aligned)

// Single contiguous global scratch: g_M | g_cs | g_cnt  (one memset per launch).
#define G_M_OFF   0
#define G_CS_OFF  (BHN * DD * DD)
#define G_CNT_OFF (G_CS_OFF + BHN * DD)
#define G_TOTAL   (G_CNT_OFF + BHN)
__device__ float g_scratch[G_TOTAL];

// smem layout (bytes):
//  A: 0     .. 9216   EsT [64][PH1] bf16 (8448) | later dotT [64][PH2] bf16 (9216)
//  B: 9216  .. 17664  VsT [64][PH1] bf16 (8448)
//     (A+B reused after GEMM2 as otile [64][PVO] f32 = 17408 <= 17664)
//  C: 17664 .. 26880  Qsm [64][PH2] bf16 (9216)
//  D: 26880 .. 44288  Vf32 [64][PVO] f32 (17408)
//  E: 44288 .. 44544  scs [64] f32
//  F: 44544 .. 45056  sidx [128] int
#define SM_A 0
#define SM_B 9216
#define SM_C 17664
#define SM_D 26880
#define SM_E 44288
#define SM_F 44544
#define SM_TOTAL 45056   // 5 blocks/SM: 225,280 B <= 227 KB carveout

__device__ __forceinline__ void mma_bf16(float* d,
    unsigned a0, unsigned a1, unsigned a2, unsigned a3, unsigned b0, unsigned b1) {
    asm("mma.sync.aligned.m16n8k16.row.col.f32.bf16.bf16.f32 "
        "{%0,%1,%2,%3}, {%4,%5,%6,%7}, {%8,%9}, {%0,%1,%2,%3};"
        : "+f"(d[0]), "+f"(d[1]), "+f"(d[2]), "+f"(d[3])
        : "r"(a0), "r"(a1), "r"(a2), "r"(a3), "r"(b0), "r"(b1));
}
__device__ __forceinline__ void red_add_v4(float* p, float a, float b, float c, float d) {
    asm volatile("red.global.add.v4.f32 [%0], {%1,%2,%3,%4};"
                 :: "l"(p), "f"(a), "f"(b), "f"(c), "f"(d) : "memory");
}
__device__ __forceinline__ void red_add_v2(float* p, float a, float b) {
    asm volatile("red.global.add.v2.f32 [%0], {%1,%2};"
                 :: "l"(p), "f"(a), "f"(b) : "memory");
}
__device__ __forceinline__ float warp_sum(float v) {
    #pragma unroll
    for (int o = 16; o; o >>= 1) v += __shfl_xor_sync(0xffffffffu, v, o);
    return v;
}
__device__ __forceinline__ unsigned ldu32(const __nv_bfloat16* p) {
    return *reinterpret_cast<const unsigned*>(p);
}

// Fused: zero out-slice + gather/softmax (tiles kept resident in smem) + GEMM1 ->
// red.add g_M -> release counter -> spin for bh completion -> dotT -> GEMM2 ->
// epilogue scatter (V from smem, out pre-zeroed by same-bh blocks).
__global__ void __launch_bounds__(NT, 5) k_fused(
    const float* __restrict__ Q, const float* __restrict__ V,
    const int* __restrict__ idxq, const int* __restrict__ idxk,
    float* __restrict__ out, float scaleA, float scaleB, int S)
{
    extern __shared__ char smraw[];
    __nv_bfloat16* EsT  = reinterpret_cast<__nv_bfloat16*>(smraw + SM_A);
    __nv_bfloat16* VsT  = reinterpret_cast<__nv_bfloat16*>(smraw + SM_B);
    __nv_bfloat16* Qsm  = reinterpret_cast<__nv_bfloat16*>(smraw + SM_C);
    float*         Vf   = reinterpret_cast<float*>(smraw + SM_D);
    float*         scs  = reinterpret_cast<float*>(smraw + SM_E);
    int*           sidx = reinterpret_cast<int*>(smraw + SM_F);
    __nv_bfloat16* dotT  = reinterpret_cast<__nv_bfloat16*>(smraw + SM_A); // after GEMM1
    float*         otile = reinterpret_cast<float*>(smraw + SM_A);         // after GEMM2

    const int bh   = blockIdx.y;
    const int j0   = blockIdx.x * CH;
    const int tid  = threadIdx.x;
    const int wid  = tid >> 5;
    const int lane = tid & 31;

    float*    g_M   = g_scratch + G_M_OFF;
    float*    g_cs  = g_scratch + G_CS_OFF;
    unsigned* g_cnt = reinterpret_cast<unsigned*>(g_scratch + G_CNT_OFF);

    // Phase 0: zero this block's slice of out. Blocks (x,y) with x=0..31 cover
    // exactly bh=y's 262144 floats; scatter for bh y waits on g_cnt[y]==32,
    // which happens-after all 32 blocks' zeroing (membar before release).
    {
        const float4 z4 = make_float4(0.f, 0.f, 0.f, 0.f);
        float4* o4 = reinterpret_cast<float4*>(out)
                   + (size_t)(blockIdx.y * gridDim.x + blockIdx.x) * 2048;
        #pragma unroll
        for (int i = 0; i < 8; i++) o4[tid + i * NT] = z4;
    }

    const float* Qb = Q + (size_t)bh * S * DD;
    const float* Vb = V + (size_t)bh * S * DD;
    float* outb = out + (size_t)bh * S * DD;

    if (tid < CH)           sidx[tid] = idxq[j0 + tid];
    else if (tid < 2 * CH)  sidx[tid] = idxk[j0 + tid - CH];
    if (tid < DD) scs[tid] = 0.f;
    __syncthreads();

    // Phase 1: gather + softmax. Keeps Qsm (bf16), E=exp(Qsm) (bf16,T),
    // V (bf16,T and f32 row-major) all in smem. No max-subtraction needed.
    float csA = 0.f, csB = 0.f;
    for (int r = wid * 4; r < CH; r += 32) {
        float2 q[4], v[4];
        #pragma unroll
        for (int t = 0; t < 4; t++) {
            q[t] = reinterpret_cast<const float2*>(Qb + (size_t)sidx[r + t] * DD)[lane];
            v[t] = reinterpret_cast<const float2*>(Vb + (size_t)sidx[CH + r + t] * DD)[lane];
        }
        #pragma unroll
        for (int t = 0; t < 4; t++) {
            const int rr = r + t;
            float e0 = __expf(q[t].x), e1 = __expf(q[t].y);
            float inv = __fdividef(1.f, warp_sum(e0 + e1));
            float s0 = e0 * inv, s1 = e1 * inv;
            __nv_bfloat162 h2 = __floats2bfloat162_rn(s0, s1);
            *reinterpret_cast<unsigned*>(Qsm + rr * PH2 + 2 * lane)
                = *reinterpret_cast<unsigned*>(&h2);
            *reinterpret_cast<float2*>(Vf + rr * PVO + 2 * lane) = v[t];
            float E0 = __expf(s0), E1 = __expf(s1);
            EsT[(2 * lane) * PH1 + rr]     = __float2bfloat16(E0);
            EsT[(2 * lane + 1) * PH1 + rr] = __float2bfloat16(E1);
            VsT[(2 * lane) * PH1 + rr]     = __float2bfloat16(v[t].x);
            VsT[(2 * lane + 1) * PH1 + rr] = __float2bfloat16(v[t].y);
            csA += E0; csB += E1;
        }
    }
    atomicAdd(&scs[2 * lane],     csA);
    atomicAdd(&scs[2 * lane + 1], csB);
    __syncthreads();
    if (tid < DD) atomicAdd(&g_cs[bh * DD + tid], scs[tid]);

    // Phase 2: GEMM1 (bf16 m16n8k16): M=64(d) x N=64(e) x K=64(s) -> red to g_M.
    const int l4 = lane >> 2, lm = lane & 3;
    const int wm = wid & 1, wn = wid >> 1;
    {
        float D[2][2][4];
        #pragma unroll
        for (int mt = 0; mt < 2; mt++)
            #pragma unroll
            for (int nt = 0; nt < 2; nt++)
                #pragma unroll
                for (int u = 0; u < 4; u++) D[mt][nt][u] = 0.f;

        #pragma unroll
        for (int kc = 0; kc < CH; kc += 16) {
            unsigned a[2][4], b[2][2];
            #pragma unroll
            for (int mt = 0; mt < 2; mt++) {
                const __nv_bfloat16* ap = EsT + (wm * 32 + mt * 16 + l4) * PH1 + kc + 2 * lm;
                a[mt][0] = ldu32(ap);
                a[mt][1] = ldu32(ap + 8 * PH1);
                a[mt][2] = ldu32(ap + 8);
                a[mt][3] = ldu32(ap + 8 * PH1 + 8);
            }
            #pragma unroll
            for (int nt = 0; nt < 2; nt++) {
                const __nv_bfloat16* bp = VsT + (wn * 16 + nt * 8 + l4) * PH1 + kc + 2 * lm;
                b[nt][0] = ldu32(bp);
                b[nt][1] = ldu32(bp + 8);
            }
            #pragma unroll
            for (int mt = 0; mt < 2; mt++)
                #pragma unroll
                for (int nt = 0; nt < 2; nt++)
                    mma_bf16(D[mt][nt], a[mt][0], a[mt][1], a[mt][2], a[mt][3],
                             b[nt][0], b[nt][1]);
        }

        float* Mb = g_M + bh * DD * DD;
        #pragma unroll
        for (int mt = 0; mt < 2; mt++) {
            const int row = wm * 32 + mt * 16 + l4;
            #pragma unroll
            for (int nt = 0; nt < 2; nt++) {
                const int col = wn * 16 + nt * 8 + 2 * lm;
                red_add_v2(&Mb[row * DD + col],       D[mt][nt][0], D[mt][nt][1]);
                red_add_v2(&Mb[(row + 8) * DD + col], D[mt][nt][2], D[mt][nt][3]);
            }
        }
    }
    __syncthreads();   // all reds issued; EsT/VsT dead

    // Phase 3: publish + wait for all 32 blocks of this bh.
    if (tid == 0) {
        unsigned prev;
        asm volatile("membar.gl;" ::: "memory");
        asm volatile("atom.global.add.release.gpu.u32 %0, [%1], 1;"
                     : "=r"(prev) : "l"(&g_cnt[bh]) : "memory");
        unsigned c;
        do {
            asm volatile("ld.global.acquire.gpu.u32 %0, [%1];"
                         : "=r"(c) : "l"(&g_cnt[bh]) : "memory");
            if (c < 32) __nanosleep(64);
        } while (c < 32);
    }
    __syncthreads();

    // Phase 4: dotT[e][d] = bf16(M[d][e] / cs[d]) into region A.
    {
        const float* Mb = g_M + bh * DD * DD;
        const int d  = tid >> 2;
        const int e0 = (tid & 3) * 16;
        const float inv = __fdividef(1.f, g_cs[bh * DD + d]);
        const float4* mp = reinterpret_cast<const float4*>(Mb + d * DD + e0);
        #pragma unroll
        for (int u = 0; u < 4; u++) {
            float4 m = mp[u];
            dotT[(e0 + 4 * u)     * PH2 + d] = __float2bfloat16(m.x * inv);
            dotT[(e0 + 4 * u + 1) * PH2 + d] = __float2bfloat16(m.y * inv);
            dotT[(e0 + 4 * u + 2) * PH2 + d] = __float2bfloat16(m.z * inv);
            dotT[(e0 + 4 * u + 3) * PH2 + d] = __float2bfloat16(m.w * inv);
        }
    }
    __syncthreads();

    // Phase 5: GEMM2 (bf16): M=64(j) x N=64(e) x K=64(d). A = resident Qsm.
    float D2[2][2][4];
    #pragma unroll
    for (int mt = 0; mt < 2; mt++)
        #pragma unroll
        for (int nt = 0; nt < 2; nt++)
            #pragma unroll
            for (int u = 0; u < 4; u++) D2[mt][nt][u] = 0.f;

    #pragma unroll
    for (int kc = 0; kc < DD; kc += 16) {
        unsigned a[2][4], b[2][2];
        #pragma unroll
        for (int mt = 0; mt < 2; mt++) {
            const __nv_bfloat16* ap = Qsm + (wm * 32 + mt * 16 + l4) * PH2 + kc + 2 * lm;
            a[mt][0] = ldu32(ap);
            a[mt][1] = ldu32(ap + 8 * PH2);
            a[mt][2] = ldu32(ap + 8);
            a[mt][3] = ldu32(ap + 8 * PH2 + 8);
        }
        #pragma unroll
        for (int nt = 0; nt < 2; nt++) {
            const __nv_bfloat16* bp = dotT + (wn * 16 + nt * 8 + l4) * PH2 + kc + 2 * lm;
            b[nt][0] = ldu32(bp);
            b[nt][1] = ldu32(bp + 8);
        }
        #pragma unroll
        for (int mt = 0; mt < 2; mt++)
            #pragma unroll
            for (int nt = 0; nt < 2; nt++)
                mma_bf16(D2[mt][nt], a[mt][0], a[mt][1], a[mt][2], a[mt][3],
                         b[nt][0], b[nt][1]);
    }
    __syncthreads();   // dotT dead; reuse A+B as f32 otile

    // Phase 6: stage D2 fragments into f32 otile.
    #pragma unroll
    for (int mt = 0; mt < 2; mt++) {
        const int row = wm * 32 + mt * 16 + l4;
        #pragma unroll
        for (int nt = 0; nt < 2; nt++) {
            const int col = wn * 16 + nt * 8 + 2 * lm;
            *reinterpret_cast<float2*>(&otile[row * PVO + col])
                = make_float2(D2[mt][nt][0], D2[mt][nt][1]);
            *reinterpret_cast<float2*>(&otile[(row + 8) * PVO + col])
                = make_float2(D2[mt][nt][2], D2[mt][nt][3]);
        }
    }
    __syncthreads();

    // Phase 7: epilogue. Each thread owns 16 cols of one sample row; V from smem.
    {
        const int r  = tid >> 2;
        const int co = (tid & 3) * 16;
        const int qi = sidx[r];
        const float* ot = otile + r * PVO + co;
        const float* vr = Vf + r * PVO + co;
        float* op = outb + (size_t)qi * DD + co;
        #pragma unroll
        for (int u = 0; u < 4; u++) {
            float4 v = *reinterpret_cast<const float4*>(vr + 4 * u);
            red_add_v4(op + 4 * u,
                       fmaf(scaleA, ot[4 * u],     scaleB * v.x),
                       fmaf(scaleA, ot[4 * u + 1], scaleB * v.y),
                       fmaf(scaleA, ot[4 * u + 2], scaleB * v.z),
                       fmaf(scaleA, ot[4 * u + 3], scaleB * v.w));
        }
    }
}

extern "C" void kernel_launch(void* const* d_in, const int* in_sizes, int n_in,
                              void* d_out, int out_size)
{
    const float* Q    = (const float*)d_in[0];
    const float* V    = (const float*)d_in[2];
    const int*   idxq = (const int*)d_in[4];
    const int*   idxk = (const int*)d_in[5];
    float* out = (float*)d_out;

    const int nsq = in_sizes[4];
    const int nsk = in_sizes[5];
    const int S   = in_sizes[0] / (BHN * DD);
    const float scaleA = (float)S * (float)S / ((float)nsq * (float)nsk);
    const float scaleB = (float)S / (float)nsk;

    void* sptr = nullptr; cudaGetSymbolAddress(&sptr, g_scratch);
    cudaMemsetAsync(sptr, 0, sizeof(float) * G_TOTAL);   // single scratch memset

    cudaFuncSetAttribute(k_fused, cudaFuncAttributeMaxDynamicSharedMemorySize, SM_TOTAL);

    dim3 g(nsq / CH, BHN);   // 32 x 32 = 1024 blocks
    k_fused<<<g, NT, SM_TOTAL>>>(Q, V, idxq, idxk, out, scaleA, scaleB, S);
}